// round 4
// baseline (speedup 1.0000x reference)
#include <cuda_runtime.h>
#include <cuda_bf16.h>
#include <math.h>

// Problem constants
#define NUM_EXPERTS 8
#define TOP_K 2
#define HIDDEN 512
#define INTER 2048
#define NTOK 2048            // B*S = 2*1024
#define NSLOT (NTOK * TOP_K) // 4096
#define MAXROWS 2048         // max slots a single expert can get (<= NTOK)

// ---------------- device scratch (static, allocation-free) ----------------
__device__ int   g_cnt[NUM_EXPERTS];
__device__ int   g_tok[NUM_EXPERTS][MAXROWS];
__device__ float g_wt[NUM_EXPERTS][MAXROWS];
__device__ float g_probs[NTOK * NUM_EXPERTS];
__device__ float g_hmid[(size_t)NUM_EXPERTS * MAXROWS * INTER]; // 134 MB fp32

// ---------------- helpers ----------------
__device__ __forceinline__ float gelu_tanh(float x) {
    // jax.nn.gelu default (approximate=True)
    const float c = 0.7978845608028654f; // sqrt(2/pi)
    float x3 = x * x * x;
    return 0.5f * x * (1.0f + tanhf(c * (x + 0.044715f * x3)));
}

// ---------------- kernel 0: reset counters ----------------
__global__ void reset_kernel() {
    int t = threadIdx.x;
    if (t < NUM_EXPERTS) g_cnt[t] = 0;
}

// ---------------- kernel 1: router ----------------
// One warp per token: 8 logits over H=512, softmax, top-2, renorm, bucket push.
__global__ void router_kernel(const float* __restrict__ hidden,
                              const float* __restrict__ w_router,
                              const float* __restrict__ b_router) {
    __shared__ float wsm[NUM_EXPERTS][HIDDEN]; // transposed router weights, 16 KB
    int tid = threadIdx.x;
    for (int i = tid; i < NUM_EXPERTS * HIDDEN; i += blockDim.x) {
        int e = i / HIDDEN, h = i % HIDDEN;
        wsm[e][h] = w_router[h * NUM_EXPERTS + e];
    }
    __syncthreads();

    int warp = tid >> 5, lane = tid & 31;
    int t = blockIdx.x * (blockDim.x >> 5) + warp;
    if (t >= NTOK) return;

    const float* x = hidden + (size_t)t * HIDDEN;
    float acc[NUM_EXPERTS];
#pragma unroll
    for (int e = 0; e < NUM_EXPERTS; e++) acc[e] = 0.f;

    for (int i = lane; i < HIDDEN; i += 32) {
        float xv = x[i];
#pragma unroll
        for (int e = 0; e < NUM_EXPERTS; e++) acc[e] += xv * wsm[e][i];
    }
#pragma unroll
    for (int off = 16; off > 0; off >>= 1) {
#pragma unroll
        for (int e = 0; e < NUM_EXPERTS; e++)
            acc[e] += __shfl_xor_sync(0xffffffffu, acc[e], off);
    }

    if (lane == 0) {
        float logits[NUM_EXPERTS];
        float mx = -1e30f;
#pragma unroll
        for (int e = 0; e < NUM_EXPERTS; e++) {
            logits[e] = acc[e] + b_router[e];
            mx = fmaxf(mx, logits[e]);
        }
        float p[NUM_EXPERTS];
        float Z = 0.f;
#pragma unroll
        for (int e = 0; e < NUM_EXPERTS; e++) { p[e] = __expf(logits[e] - mx); Z += p[e]; }
        float invZ = 1.0f / Z;
#pragma unroll
        for (int e = 0; e < NUM_EXPERTS; e++) {
            p[e] *= invZ;
            g_probs[t * NUM_EXPERTS + e] = p[e];
        }
        // top-2 (ties -> lower index, matching lax.top_k)
        int i1 = 0; float p1 = p[0];
#pragma unroll
        for (int e = 1; e < NUM_EXPERTS; e++) if (p[e] > p1) { p1 = p[e]; i1 = e; }
        int i2 = -1; float p2 = -1.0f;
#pragma unroll
        for (int e = 0; e < NUM_EXPERTS; e++) {
            if (e != i1 && p[e] > p2) { p2 = p[e]; i2 = e; }
        }
        float rs = 1.0f / (p1 + p2);
        int pos1 = atomicAdd(&g_cnt[i1], 1);
        g_tok[i1][pos1] = t; g_wt[i1][pos1] = p1 * rs;
        int pos2 = atomicAdd(&g_cnt[i2], 1);
        g_tok[i2][pos2] = t; g_wt[i2][pos2] = p2 * rs;
    }
}

// ---------------- kernel 2: balance loss (deterministic reduce) ----------------
__global__ void loss_kernel(float* __restrict__ out, int write_loss) {
    __shared__ float red[256];
    int tid = threadIdx.x;
    float loss_acc = 0.f;
    for (int e = 0; e < NUM_EXPERTS; e++) {
        float s = 0.f;
        for (int t = tid; t < NTOK; t += 256)
            s += g_probs[t * NUM_EXPERTS + e];
        red[tid] = s;
        __syncthreads();
        for (int off = 128; off > 0; off >>= 1) {
            if (tid < off) red[tid] += red[tid + off];
            __syncthreads();
        }
        if (tid == 0) {
            float P = red[0] / (float)NTOK;
            float f = (float)g_cnt[e] / (float)NSLOT;
            loss_acc += f * P;
        }
        __syncthreads();
    }
    if (tid == 0 && write_loss) {
        out[(size_t)NTOK * HIDDEN] = 0.01f * (float)NUM_EXPERTS * loss_acc;
    }
}

// ---------------- GEMM tiles: 64x64x16, 256 threads, 4x4 micro-tile ----------------
// GEMM1: hmid[e][m][:] = gelu( gather(hidden) @ w1[e] + b1[e] )
__global__ void __launch_bounds__(256, 4)
gemm1_kernel(const float* __restrict__ hidden,
             const float* __restrict__ w1,
             const float* __restrict__ b1) {
    int e = blockIdx.z;
    int cnt = g_cnt[e];
    int m0 = blockIdx.y * 64;
    if (m0 >= cnt) return;
    int n0 = blockIdx.x * 64;

    __shared__ float As[64][17];
    __shared__ float Bs[16][64];
    __shared__ int toks[64];

    int tid = threadIdx.x;
    if (tid < 64) {
        int m = m0 + tid;
        toks[tid] = (m < cnt) ? g_tok[e][m] : -1;
    }
    __syncthreads();

    int tx = tid & 15, ty = tid >> 4;
    float acc[4][4];
#pragma unroll
    for (int i = 0; i < 4; i++)
#pragma unroll
        for (int j = 0; j < 4; j++) acc[i][j] = 0.f;

    const float* w1e = w1 + (size_t)e * HIDDEN * INTER;

    for (int k0 = 0; k0 < HIDDEN; k0 += 16) {
        // A: 64 rows x 16 k (gathered)
#pragma unroll
        for (int r = 0; r < 4; r++) {
            int idx = tid + r * 256;
            int m = idx >> 4, kk = idx & 15;
            int tok = toks[m];
            As[m][kk] = (tok >= 0) ? hidden[(size_t)tok * HIDDEN + k0 + kk] : 0.f;
        }
        // B: 16 k x 64 n
#pragma unroll
        for (int r = 0; r < 4; r++) {
            int idx = tid + r * 256;
            int kk = idx >> 6, n = idx & 63;
            Bs[kk][n] = w1e[(size_t)(k0 + kk) * INTER + n0 + n];
        }
        __syncthreads();
#pragma unroll
        for (int k = 0; k < 16; k++) {
            float a0 = As[ty * 4 + 0][k];
            float a1 = As[ty * 4 + 1][k];
            float a2 = As[ty * 4 + 2][k];
            float a3 = As[ty * 4 + 3][k];
            float4 b = *(const float4*)&Bs[k][tx * 4];
            acc[0][0] += a0 * b.x; acc[0][1] += a0 * b.y; acc[0][2] += a0 * b.z; acc[0][3] += a0 * b.w;
            acc[1][0] += a1 * b.x; acc[1][1] += a1 * b.y; acc[1][2] += a1 * b.z; acc[1][3] += a1 * b.w;
            acc[2][0] += a2 * b.x; acc[2][1] += a2 * b.y; acc[2][2] += a2 * b.z; acc[2][3] += a2 * b.w;
            acc[3][0] += a3 * b.x; acc[3][1] += a3 * b.y; acc[3][2] += a3 * b.z; acc[3][3] += a3 * b.w;
        }
        __syncthreads();
    }

    float4 bb = *(const float4*)&b1[(size_t)e * INTER + n0 + tx * 4];
#pragma unroll
    for (int i = 0; i < 4; i++) {
        int m = m0 + ty * 4 + i;
        if (m < cnt) {
            float4 v;
            v.x = gelu_tanh(acc[i][0] + bb.x);
            v.y = gelu_tanh(acc[i][1] + bb.y);
            v.z = gelu_tanh(acc[i][2] + bb.z);
            v.w = gelu_tanh(acc[i][3] + bb.w);
            *(float4*)&g_hmid[((size_t)e * MAXROWS + m) * INTER + n0 + tx * 4] = v;
        }
    }
}

// GEMM2: out[tok] += wt * ( hmid[e] @ w2[e] + b2[e] )
__global__ void __launch_bounds__(256, 4)
gemm2_kernel(const float* __restrict__ w2,
             const float* __restrict__ b2,
             float* __restrict__ out) {
    int e = blockIdx.z;
    int cnt = g_cnt[e];
    int m0 = blockIdx.y * 64;
    if (m0 >= cnt) return;
    int n0 = blockIdx.x * 64;

    __shared__ float As[64][17];
    __shared__ float Bs[16][64];

    int tid = threadIdx.x;
    int tx = tid & 15, ty = tid >> 4;
    float acc[4][4];
#pragma unroll
    for (int i = 0; i < 4; i++)
#pragma unroll
        for (int j = 0; j < 4; j++) acc[i][j] = 0.f;

    const float* w2e = w2 + (size_t)e * INTER * HIDDEN;
    const float* ae  = &g_hmid[(size_t)e * MAXROWS * INTER];

    for (int k0 = 0; k0 < INTER; k0 += 16) {
#pragma unroll
        for (int r = 0; r < 4; r++) {
            int idx = tid + r * 256;
            int m = idx >> 4, kk = idx & 15;
            int gm = m0 + m;
            As[m][kk] = (gm < cnt) ? ae[(size_t)gm * INTER + k0 + kk] : 0.f;
        }
#pragma unroll
        for (int r = 0; r < 4; r++) {
            int idx = tid + r * 256;
            int kk = idx >> 6, n = idx & 63;
            Bs[kk][n] = w2e[(size_t)(k0 + kk) * HIDDEN + n0 + n];
        }
        __syncthreads();
#pragma unroll
        for (int k = 0; k < 16; k++) {
            float a0 = As[ty * 4 + 0][k];
            float a1 = As[ty * 4 + 1][k];
            float a2 = As[ty * 4 + 2][k];
            float a3 = As[ty * 4 + 3][k];
            float4 b = *(const float4*)&Bs[k][tx * 4];
            acc[0][0] += a0 * b.x; acc[0][1] += a0 * b.y; acc[0][2] += a0 * b.z; acc[0][3] += a0 * b.w;
            acc[1][0] += a1 * b.x; acc[1][1] += a1 * b.y; acc[1][2] += a1 * b.z; acc[1][3] += a1 * b.w;
            acc[2][0] += a2 * b.x; acc[2][1] += a2 * b.y; acc[2][2] += a2 * b.z; acc[2][3] += a2 * b.w;
            acc[3][0] += a3 * b.x; acc[3][1] += a3 * b.y; acc[3][2] += a3 * b.z; acc[3][3] += a3 * b.w;
        }
        __syncthreads();
    }

    float4 bb = *(const float4*)&b2[(size_t)e * HIDDEN + n0 + tx * 4];
#pragma unroll
    for (int i = 0; i < 4; i++) {
        int m = m0 + ty * 4 + i;
        if (m < cnt) {
            float w = g_wt[e][m];
            int tok = g_tok[e][m];
            float* op = out + (size_t)tok * HIDDEN + n0 + tx * 4;
            atomicAdd(op + 0, (acc[i][0] + bb.x) * w);
            atomicAdd(op + 1, (acc[i][1] + bb.y) * w);
            atomicAdd(op + 2, (acc[i][2] + bb.z) * w);
            atomicAdd(op + 3, (acc[i][3] + bb.w) * w);
        }
    }
}

// ---------------- launch ----------------
extern "C" void kernel_launch(void* const* d_in, const int* in_sizes, int n_in,
                              void* d_out, int out_size) {
    const float* hidden   = (const float*)d_in[0]; // (2,1024,512)
    const float* w_router = (const float*)d_in[1]; // (512,8)
    const float* b_router = (const float*)d_in[2]; // (8,)
    const float* w1       = (const float*)d_in[3]; // (8,512,2048)
    const float* b1       = (const float*)d_in[4]; // (8,2048)
    const float* w2       = (const float*)d_in[5]; // (8,2048,512)
    const float* b2       = (const float*)d_in[6]; // (8,512)
    float* out = (float*)d_out;

    // residual init: out[:NTOK*H] = hidden
    cudaMemcpyAsync(out, hidden, (size_t)NTOK * HIDDEN * sizeof(float),
                    cudaMemcpyDeviceToDevice);

    reset_kernel<<<1, 32>>>();
    router_kernel<<<NTOK / 8, 256>>>(hidden, w_router, b_router);

    int write_loss = (out_size > NTOK * HIDDEN) ? 1 : 0;
    loss_kernel<<<1, 256>>>(out, write_loss);

    // GEMM1: n tiles = INTER/64 = 32, m tiles up to 32, 8 experts
    gemm1_kernel<<<dim3(INTER / 64, MAXROWS / 64, NUM_EXPERTS), 256>>>(hidden, w1, b1);
    // GEMM2: n tiles = HIDDEN/64 = 8
    gemm2_kernel<<<dim3(HIDDEN / 64, MAXROWS / 64, NUM_EXPERTS), 256>>>(w2, b2, out);
}